// round 14
// baseline (speedup 1.0000x reference)
#include <cuda_runtime.h>
#include <cuda_fp16.h>
#include <cstdint>

// ============================================================================
// BG_LSTM: B=512, T=512, H=256, input size 1.
// Persistent HMMA kernel (no tcgen05 at harness .target sm_103).
// 128 CTAs = 4 batch-groups(M=128) x 32 hidden-tiles (8 hidden -> N=32 gate
// cols). Per step: D[128,32] = A[128,256] @ B[32,256]^T, single fp16 split.
// B (W_hh) fragments pinned in registers across all 512 steps.
// Group barrier = 32-slot flag array (st.release / ld.acquire), no atomics.
// x LDG hoisted above the flag wait (input is CTA-independent).
// ============================================================================

static constexpr int Bsz = 512, Tsz = 512, Hsz = 256;
static constexpr int MTILES = 4, NTILES = 32;
static constexpr int MB = 128, NCOL = 32, NH = 8;

// SMEM layout (bytes)
static constexpr int SM_BIAS = 0;                   // 32 floats
static constexpr int SM_WIH  = 128;                 // 32 floats
static constexpr int SM_A    = 1024;                // A tile 128x256 fp16 = 65536
static constexpr int SM_BHI  = SM_A + 65536;        // 66560, W_hh fp16 16384
static constexpr int SM_DST  = SM_BHI + 16384;      // 82944; 128*36*4 = 18432
static constexpr int SM_TOTAL = SM_DST + 18432;     // 101376

// Device scratch (static — no allocation)
__device__ __half g_h[2][Bsz * Hsz];        // double-buffered h state
__device__ int    g_flag[MTILES][NTILES];   // per-CTA step flags (monotonic)
__device__ float  g_part[Bsz][NTILES];      // fc partials

// ---------------------------------------------------------------------------
// helpers
// ---------------------------------------------------------------------------
__device__ __forceinline__ uint32_t smem_to_u32(const void* p) {
    uint32_t a;
    asm("{ .reg .u64 t; cvta.to.shared.u64 t, %1; cvt.u32.u64 %0, t; }"
        : "=r"(a) : "l"(p));
    return a;
}

// Swizzled offsets: XOR ((r&7)<<4) onto byte bits[4:6] -> conflict-free.
__device__ __forceinline__ uint32_t aoff(int r, int c) {  // A: 128 x 256 fp16
    return (uint32_t)(((c >> 6) * 16 + (r >> 3)) * 1024)
         + (uint32_t)((r & 7) * 128)
         + (((uint32_t)((c & 63) * 2)) ^ ((uint32_t)(r & 7) << 4));
}
__device__ __forceinline__ uint32_t boff(int r, int c) {  // B: 32 x 256 fp16
    return (uint32_t)(((c >> 6) * 4 + (r >> 3)) * 1024)
         + (uint32_t)((r & 7) * 128)
         + (((uint32_t)((c & 63) * 2)) ^ ((uint32_t)(r & 7) << 4));
}

__device__ __forceinline__ void ldsm4(uint32_t* r, uint32_t addr) {
    asm volatile("ldmatrix.sync.aligned.m8n8.x4.shared.b16 {%0,%1,%2,%3}, [%4];"
        : "=r"(r[0]), "=r"(r[1]), "=r"(r[2]), "=r"(r[3]) : "r"(addr));
}

__device__ __forceinline__ void mma16816(float* c, const uint32_t* a,
                                         uint32_t b0, uint32_t b1) {
    asm volatile(
        "mma.sync.aligned.m16n8k16.row.col.f32.f16.f16.f32 "
        "{%0,%1,%2,%3}, {%4,%5,%6,%7}, {%8,%9}, {%0,%1,%2,%3};"
        : "+f"(c[0]), "+f"(c[1]), "+f"(c[2]), "+f"(c[3])
        : "r"(a[0]), "r"(a[1]), "r"(a[2]), "r"(a[3]), "r"(b0), "r"(b1));
}

__device__ __forceinline__ int ld_acquire(const int* p) {
    int v;
    asm volatile("ld.acquire.gpu.global.b32 %0, [%1];" : "=r"(v) : "l"(p) : "memory");
    return v;
}
__device__ __forceinline__ void st_release(int* p, int v) {
    asm volatile("st.release.gpu.global.b32 [%0], %1;" :: "l"(p), "r"(v) : "memory");
}

__device__ __forceinline__ float sigf(float x) {
    return __fdividef(1.f, 1.f + __expf(-x));
}
__device__ __forceinline__ float tanhf_acc(float x) {
    return __fdividef(2.f, 1.f + __expf(-2.f * x)) - 1.f;
}

// ---------------------------------------------------------------------------
// init: zero h buffer 0 + flags (runs every graph replay)
// ---------------------------------------------------------------------------
__global__ void lstm_init_kernel() {
    int tid = blockIdx.x * blockDim.x + threadIdx.x;
    int nth = gridDim.x * blockDim.x;
    uint4 z = make_uint4(0, 0, 0, 0);
    uint4* p = reinterpret_cast<uint4*>(&g_h[0][0]);
    int n16 = (Bsz * Hsz * 2) / 16;   // buffer 0 only (buf1 fully overwritten at t=0)
    for (int i = tid; i < n16; i += nth) p[i] = z;
    int* f = &g_flag[0][0];
    for (int i = tid; i < MTILES * NTILES; i += nth) f[i] = 0;
}

// ---------------------------------------------------------------------------
// main persistent kernel: 128 CTAs x 128 threads
// ---------------------------------------------------------------------------
__global__ void __launch_bounds__(128, 1) lstm_main_kernel(
    const float* __restrict__ x,     const float* __restrict__ W_ih,
    const float* __restrict__ W_hh,  const float* __restrict__ b_ih,
    const float* __restrict__ b_hh,  const float* __restrict__ W_fc,
    const float* __restrict__ b_fc,  float* __restrict__ out)
{
    extern __shared__ char smem[];
    const uint32_t sb = smem_to_u32(smem);
    const int tid = threadIdx.x, wid = tid >> 5, lid = tid & 31;
    const int bidx = blockIdx.x;
    const int mtile = bidx >> 5, ntile = bidx & 31;
    const int n0 = ntile * NH;
    const int mi = wid >> 1, ni = wid & 1;     // 2x2 warp split: m64 x n16

    // --- build stationary B (W_hh slice) fp16, swizzled ---
    // B row r: gate = r&3, hidden j = r>>2  (gate-minor for epilogue locality)
    for (int idx = tid; idx < NCOL * Hsz; idx += 128) {
        int r = idx >> 8, c = idx & 255;
        int gate = r & 3, j = r >> 2;
        float w = W_hh[(gate * Hsz + n0 + j) * Hsz + c];
        *reinterpret_cast<__half*>(smem + SM_BHI + boff(r, c)) = __float2half(w);
    }
    if (tid < NCOL) {
        int gate = tid & 3, j = tid >> 2;
        int grow = gate * Hsz + n0 + j;
        reinterpret_cast<float*>(smem + SM_BIAS)[tid] = b_ih[grow] + b_hh[grow];
        reinterpret_cast<float*>(smem + SM_WIH)[tid]  = W_ih[grow];
    }
    __syncthreads();

    // ldmatrix lane-role constants
    const int matA = lid >> 3;
    const int rA_l = (matA & 1) * 8 + (lid & 7);
    const int cA_l = (matA >> 1) * 8;
    const int rB_l = ni * 16 + (matA >> 1) * 8 + (lid & 7);
    const int cB_l = (matA & 1) * 8;

    // --- preload ALL B fragments into registers (stationary across 512 steps)
    uint32_t bfr[16][4];
#pragma unroll
    for (int kt = 0; kt < 16; ++kt)
        ldsm4(bfr[kt], sb + SM_BHI + boff(rB_l, kt * 16 + cB_l));

    // per-thread LSTM state: thread t owns batch row (mtile*128 + t), 8 units
    float cst[NH], hq[NH];
#pragma unroll
    for (int j = 0; j < NH; ++j) { cst[j] = 0.f; hq[j] = 0.f; }
    const int myrow = mtile * MB + tid;

    const float* bs = reinterpret_cast<const float*>(smem + SM_BIAS);
    const float* ws = reinterpret_cast<const float*>(smem + SM_WIH);

    for (int t = 0; t < Tsz; ++t) {
        // 0. prefetch x for this step (input is CTA-independent -> overlap
        //    its latency with the inter-CTA wait)
        const float xv = x[myrow * Tsz + t];

        // 1. wait for all 32 producers of h(t): warp 0 lanes poll own slot
        if (t > 0 && wid == 0) {
            int spins = 0;
            while (ld_acquire(&g_flag[mtile][lid]) < t && spins < (1 << 27)) ++spins;
        }
        __syncthreads();

        // 2. A-build: coalesced LDG of h(t), swizzled STS
        {
            const __half* hsrc = g_h[t & 1];
            const int c0 = lid * 8;
#pragma unroll 8
            for (int rr = 0; rr < 32; ++rr) {
                int r = wid * 32 + rr;
                uint4 v = *reinterpret_cast<const uint4*>(
                    hsrc + (mtile * MB + r) * Hsz + c0);
                *reinterpret_cast<uint4*>(smem + SM_A + aoff(r, c0)) = v;
            }
        }
        __syncthreads();

        // 3. MMA: single fp16 split, B from registers
        float acc[4][2][4];
#pragma unroll
        for (int a = 0; a < 4; ++a)
#pragma unroll
            for (int b = 0; b < 2; ++b)
#pragma unroll
                for (int k = 0; k < 4; ++k) acc[a][b][k] = 0.f;

#pragma unroll
        for (int kt = 0; kt < 16; ++kt) {
            uint32_t afr[4][4];
#pragma unroll
            for (int mt = 0; mt < 4; ++mt)
                ldsm4(afr[mt], sb + SM_A + aoff(mi * 64 + mt * 16 + rA_l, kt * 16 + cA_l));
#pragma unroll
            for (int mt = 0; mt < 4; ++mt) {
                mma16816(acc[mt][0], afr[mt], bfr[kt][0], bfr[kt][1]);
                mma16816(acc[mt][1], afr[mt], bfr[kt][2], bfr[kt][3]);
            }
        }

        // 4. stage D to SMEM (pad 36 floats/row)
        {
            const int r0 = mi * 64 + (lid >> 2);
            const int cc = ni * 16 + 2 * (lid & 3);
#pragma unroll
            for (int mt = 0; mt < 4; ++mt) {
#pragma unroll
                for (int nt = 0; nt < 2; ++nt) {
                    int row = r0 + mt * 16, col = cc + nt * 8;
                    *reinterpret_cast<float2*>(smem + SM_DST + (row * 36 + col) * 4) =
                        make_float2(acc[mt][nt][0], acc[mt][nt][1]);
                    *reinterpret_cast<float2*>(smem + SM_DST + ((row + 8) * 36 + col) * 4) =
                        make_float2(acc[mt][nt][2], acc[mt][nt][3]);
                }
            }
        }
        __syncthreads();

        // 5. epilogue: thread t = row t; gates (i,f,g,o per unit j, float4)
        {
            const float4* drow = reinterpret_cast<const float4*>(
                smem + SM_DST + tid * 36 * 4);
            const float4* ws4 = reinterpret_cast<const float4*>(ws);
            const float4* bs4 = reinterpret_cast<const float4*>(bs);
            uint32_t pk[4];
#pragma unroll
            for (int j = 0; j < NH; ++j) {
                float4 d4 = drow[j], w4 = ws4[j], b4 = bs4[j];
                float gi = d4.x + xv * w4.x + b4.x;
                float gf = d4.y + xv * w4.y + b4.y;
                float gg = d4.z + xv * w4.z + b4.z;
                float go = d4.w + xv * w4.w + b4.w;
                float i_ = sigf(gi), f_ = sigf(gf);
                float g_ = tanhf_acc(gg), o_ = sigf(go);
                cst[j] = f_ * cst[j] + i_ * g_;
                float h = o_ * tanhf_acc(cst[j]);
                hq[j] = h;
                unsigned short u = __half_as_ushort(__float2half(h));
                if (j & 1) pk[j >> 1] |= ((uint32_t)u) << 16;
                else       pk[j >> 1]  = (uint32_t)u;
            }
            *reinterpret_cast<uint4*>(&g_h[(t + 1) & 1][myrow * Hsz + n0]) =
                make_uint4(pk[0], pk[1], pk[2], pk[3]);
        }
        __syncthreads();
        if (tid == 0) st_release(&g_flag[mtile][ntile], t + 1);
    }

    // --- FC head: relu(h) @ W_fc^T + b_fc, flag-synced 2-phase reduce ---
    {
        float p = 0.f;
#pragma unroll
        for (int j = 0; j < NH; ++j) {
            float h = hq[j] > 0.f ? hq[j] : 0.f;
            p += h * W_fc[n0 + j];
        }
        g_part[myrow][ntile] = p;
        __syncthreads();
        if (tid == 0) st_release(&g_flag[mtile][ntile], Tsz + 2);
        if (ntile == 0) {
            if (wid == 0) {
                int spins = 0;
                while (ld_acquire(&g_flag[mtile][lid]) < Tsz + 2 && spins < (1 << 27)) ++spins;
            }
            __syncthreads();
            float acc = b_fc[0];
#pragma unroll
            for (int nt = 0; nt < NTILES; ++nt) acc += g_part[myrow][nt];
            out[myrow] = acc;
        }
    }
}

// ---------------------------------------------------------------------------
// kernel_launch
// ---------------------------------------------------------------------------
extern "C" void kernel_launch(void* const* d_in, const int* in_sizes, int n_in,
                              void* d_out, int out_size) {
    (void)in_sizes; (void)n_in; (void)out_size;
    const float* x    = (const float*)d_in[0];
    const float* W_ih = (const float*)d_in[1];
    const float* W_hh = (const float*)d_in[2];
    const float* b_ih = (const float*)d_in[3];
    const float* b_hh = (const float*)d_in[4];
    const float* W_fc = (const float*)d_in[5];
    const float* b_fc = (const float*)d_in[6];
    float* out = (float*)d_out;

    cudaFuncSetAttribute(lstm_main_kernel,
                         cudaFuncAttributeMaxDynamicSharedMemorySize, SM_TOTAL);

    lstm_init_kernel<<<64, 256>>>();
    lstm_main_kernel<<<MTILES * NTILES, 128, SM_TOTAL>>>(
        x, W_ih, W_hh, b_ih, b_hh, W_fc, b_fc, out);
}